// round 9
// baseline (speedup 1.0000x reference)
#include <cuda_runtime.h>
#include <cstdint>

#define NN 10000
#define BB 32
#define EE 40000
#define HH 4
#define DD 10
#define TT 10
#define FP 12      // padded feat row (floats)
#define NEG 0.2f

// ---------------- scratch ----------------
__device__ float  g_feat[2][(size_t)NN * BB * FP];   // fp32 feats (N,B,12), 2 ch
__device__ float  g_el[4][(size_t)NN * BB * HH];     // (N,B,H) float4-friendly
__device__ float  g_er[4][(size_t)NN * BB * HH];
__device__ float  g_g[4][(size_t)NN * DD * BB];      // (N,D,B)
__device__ float  g_rm[2][(size_t)NN * BB];          // regression heads (mu, sg)
__device__ float  g_ul[2][4][HH][TT];
__device__ float  g_ur[2][4][HH][TT];
__device__ double g_stats2[4][2][256];
__device__ double g_stats[4][2];
__device__ int    g_deg[2][NN];
__device__ int    g_rowstart[2][NN + 1];
__device__ int    g_cursor[2][NN];
__device__ int    g_csrc[2][EE];

struct Params { const float* fc[4]; };
struct PP { const float* fc[2][4]; const float* al[2][4]; const float* ar[2][4]; };

// ---------------- f32x2 helpers ----------------
__device__ __forceinline__ void fma2(unsigned long long& d, unsigned long long a, unsigned long long b) {
    asm("fma.rn.f32x2 %0, %1, %2, %0;" : "+l"(d) : "l"(a), "l"(b));
}
__device__ __forceinline__ unsigned long long pack2(float x, float y) {
    unsigned long long r; asm("mov.b64 %0, {%1, %2};" : "=l"(r) : "f"(x), "f"(y)); return r;
}
__device__ __forceinline__ void unpack2(unsigned long long v, float& x, float& y) {
    asm("mov.b64 {%0, %1}, %2;" : "=f"(x), "=f"(y) : "l"(v));
}

// ---------------- zero + compute_u fused ----------------
__global__ void zero_kernel(PP p) {
    int i = blockIdx.x * blockDim.x + threadIdx.x;
    if (i < 2 * NN) ((int*)g_deg)[i] = 0;
    if (i < 4 * 2 * 256) ((double*)g_stats2)[i] = 0.0;
    if (i >= 2 * NN && i < 2 * NN + 2 * 4 * HH * TT) {
        int j = i - 2 * NN;
        int t = j % TT;
        int h = (j / TT) % HH;
        int v = (j / (TT * HH)) % 4;
        int s = j / (TT * HH * 4);
        float ul = 0.f, ur = 0.f;
#pragma unroll
        for (int d = 0; d < DD; d++) {
            float w = p.fc[s][v][(h * DD + d) * TT + t];
            ul += p.al[s][v][h * DD + d] * w;
            ur += p.ar[s][v][h * DD + d] * w;
        }
        g_ul[s][v][h][t] = ul;
        g_ur[s][v][h][t] = ur;
    }
}

__global__ void count_kernel(const int* __restrict__ ps_dst, const int* __restrict__ rl_dst) {
    int e = blockIdx.x * blockDim.x + threadIdx.x;
    if (e >= EE) return;
    atomicAdd(&g_deg[0][ps_dst[e]], 1);
    atomicAdd(&g_deg[1][rl_dst[e]], 1);
}

// 2 blocks: one per graph
__global__ void scan_kernel() {
    __shared__ int sh[1024];
    int t = threadIdx.x;
    int g = blockIdx.x;
    const int CH = 10;
    int base = t * CH;
    int loc[CH];
    int s = 0;
#pragma unroll
    for (int i = 0; i < CH; i++) {
        int idx = base + i;
        int v = (idx < NN) ? g_deg[g][idx] : 0;
        loc[i] = s; s += v;
    }
    sh[t] = s;
    __syncthreads();
    for (int off = 1; off < 1024; off <<= 1) {
        int v = (t >= off) ? sh[t - off] : 0;
        __syncthreads();
        sh[t] += v;
        __syncthreads();
    }
    int excl = (t > 0) ? sh[t - 1] : 0;
#pragma unroll
    for (int i = 0; i < CH; i++) {
        int idx = base + i;
        if (idx < NN) {
            int rs = excl + loc[i];
            g_rowstart[g][idx] = rs;
            g_cursor[g][idx] = rs;
        }
    }
    if (t == 1023) g_rowstart[g][NN] = sh[1023];
}

__global__ void fill_kernel(const int* __restrict__ ps_src, const int* __restrict__ ps_dst,
                            const int* __restrict__ rl_src, const int* __restrict__ rl_dst) {
    int e = blockIdx.x * blockDim.x + threadIdx.x;
    if (e >= EE) return;
    int p = atomicAdd(&g_cursor[0][ps_dst[e]], 1);
    g_csrc[0][p] = ps_src[e];
    p = atomicAdd(&g_cursor[1][rl_dst[e]], 1);
    g_csrc[1][p] = rl_src[e];
}

// ---------------- prep: feats fp32 (N,B,12) + el/er float4 (N,B,H); stage0 also rm/rs ----------------
__global__ void __launch_bounds__(128) prep_kernel(const float* __restrict__ x, int stage,
                                                   const float* __restrict__ wmu, const float* __restrict__ bmu,
                                                   const float* __restrict__ wsg, const float* __restrict__ bsg) {
    __shared__ float sx[TT][BB * 3];
    __shared__ float sf[2][TT][BB];
    __shared__ float sul[4][HH][TT], sur[4][HH][TT];
    __shared__ float smean[4], srstd[4];
    __shared__ float swm[TT], sws[TT], sb[2];
    int n = blockIdx.x;
    int tid = threadIdx.x;
    int b = tid & 31, vv = tid >> 5;

    for (int i = tid; i < 4 * HH * TT; i += 128) {
        int t = i % TT, hh = (i / TT) % HH, v = i / (TT * HH);
        sul[v][hh][t] = g_ul[stage][v][hh][t];
        sur[v][hh][t] = g_ur[stage][v][hh][t];
    }
    if (stage == 0) {
        if (tid < TT) { swm[tid] = wmu[tid]; sws[tid] = wsg[tid]; }
        if (tid == 10) sb[0] = bmu[0];
        if (tid == 11) sb[1] = bsg[0];
        for (int i = tid; i < TT * 96; i += 128) {
            int t = i / 96, j = i % 96;
            sx[t][j] = x[((size_t)t * NN + n) * 96 + j];
        }
        __syncthreads();
        for (int i = tid; i < 2 * TT * BB; i += 128) {
            int ch = i / (TT * BB), r = i % (TT * BB), t = r / BB, bb = r % BB;
            sf[ch][t][bb] = sx[t][bb * 3 + ch];
        }
        __syncthreads();
        if (vv == 2) {
            float a = sb[0];
#pragma unroll
            for (int t = 0; t < TT; t++) a += sf[0][t][b] * swm[t];
            g_rm[0][(size_t)n * BB + b] = a;
        } else if (vv == 3) {
            float a = sb[1];
#pragma unroll
            for (int t = 0; t < TT; t++) a += sf[1][t][b] * sws[t];
            g_rm[1][(size_t)n * BB + b] = a;
        }
    } else {
        if (tid < 4) {
            const double invn = 1.0 / ((double)NN * DD * BB);
            double mean = g_stats[tid][0] * invn;
            double var = g_stats[tid][1] * invn - mean * mean;
            smean[tid] = (float)mean;
            srstd[tid] = (float)rsqrt(var + 1e-5);
        }
        __syncthreads();
        for (int i = tid; i < TT * BB; i += 128) {
            int t = i / BB, bb = i % BB;
            size_t gi = ((size_t)n * DD + t) * BB + bb;
            float v0 = (g_g[0][gi] - smean[0]) * srstd[0];
            float v1 = (g_g[1][gi] - smean[1]) * srstd[1];
            float v2 = (g_g[2][gi] - smean[2]) * srstd[2];
            float v3 = (g_g[3][gi] - smean[3]) * srstd[3];
            sf[0][t][bb] = 0.5f * (v0 + v1);
            sf[1][t][bb] = 0.5f * (v2 + v3);
        }
        __syncthreads();
    }

    if (vv < 2) {
        float4* dstp = (float4*)&g_feat[vv][((size_t)n * BB + b) * FP];
        dstp[0] = make_float4(sf[vv][0][b], sf[vv][1][b], sf[vv][2][b], sf[vv][3][b]);
        dstp[1] = make_float4(sf[vv][4][b], sf[vv][5][b], sf[vv][6][b], sf[vv][7][b]);
        dstp[2] = make_float4(sf[vv][8][b], sf[vv][9][b], 0.f, 0.f);
    }

    int ch = vv & 1;
    float f[TT];
#pragma unroll
    for (int t = 0; t < TT; t++) f[t] = sf[ch][t][b];
    float elh[HH], erh[HH];
#pragma unroll
    for (int h = 0; h < HH; h++) {
        float a = 0.f, c = 0.f;
#pragma unroll
        for (int t = 0; t < TT; t++) { a += sul[vv][h][t] * f[t]; c += sur[vv][h][t] * f[t]; }
        elh[h] = a; erh[h] = c;
    }
    *(float4*)&g_el[vv][((size_t)n * BB + b) * HH] = make_float4(elh[0], elh[1], elh[2], elh[3]);
    *(float4*)&g_er[vv][((size_t)n * BB + b) * HH] = make_float4(erh[0], erh[1], erh[2], erh[3]);
}

// ---------------- GAT: two head-pair warps per (dst, variant), 2-edge pipelined ----------------
// block = 256 threads = 8 warps = 4 dsts x 2 head-pairs; blockIdx.y = variant
__global__ void __launch_bounds__(256) gat4_kernel(int stage, Params p) {
    __shared__ unsigned long long sWp[HH * DD * 5];
    __shared__ float spart[4][DD][BB];   // head-pair-1 partials, 5KB
    int v = blockIdx.y;
    int graph = stage ? (v & 1) : (v >> 1);
    int tid = threadIdx.x;
    int b = tid & 31, w = tid >> 5;
    int dslot = w >> 1;          // 0..3
    int hp = w & 1;              // head pair: heads {2hp, 2hp+1}
    int dst = blockIdx.x * 4 + dslot;

    int s0 = g_rowstart[graph][dst];
    int deg = g_rowstart[graph][dst + 1] - s0;
    float2 e2 = *(const float2*)&g_er[v][((size_t)dst * BB + b) * HH + 2 * hp];

    // stage W (ordered before epilogue by the post-mainloop barrier)
    for (int i = tid; i < HH * DD * 5; i += 256) {
        int row = i / 5, tp = i % 5;
        sWp[i] = pack2(p.fc[v][row * TT + 2 * tp], p.fc[v][row * TT + 2 * tp + 1]);
    }

    float erh[2] = {e2.x, e2.y};
    const float* elb = g_el[v];
    const float* featb = g_feat[v & 1];
    const int* csrcp = g_csrc[graph];

    unsigned long long acc[2][5];
    float Z[2];
#pragma unroll
    for (int h = 0; h < 2; h++) {
        Z[h] = 0.f;
#pragma unroll
        for (int t = 0; t < 5; t++) acc[h][t] = 0ull;
    }

    for (int base = 0; base < deg; base += 32) {
        int cnt = min(32, deg - base);
        int myS = (b < cnt) ? csrcp[s0 + base + b] : 0;
        int k = 0;
        for (; k + 1 < cnt; k += 2) {
            int sA = __shfl_sync(0xffffffffu, myS, k);
            int sB = __shfl_sync(0xffffffffu, myS, k + 1);
            size_t sbA = (size_t)sA * BB + b;
            size_t sbB = (size_t)sB * BB + b;
            float2 evA = *(const float2*)&elb[sbA * HH + 2 * hp];
            float2 evB = *(const float2*)&elb[sbB * HH + 2 * hp];
            const float4* fbA = (const float4*)(featb + sbA * FP);
            const float4* fbB = (const float4*)(featb + sbB * FP);
            float4 fA0 = fbA[0], fA1 = fbA[1], fA2 = fbA[2];
            float4 fB0 = fbB[0], fB1 = fbB[1], fB2 = fbB[2];

            unsigned long long fpA[5], fpB[5];
            fpA[0] = pack2(fA0.x, fA0.y); fpA[1] = pack2(fA0.z, fA0.w);
            fpA[2] = pack2(fA1.x, fA1.y); fpA[3] = pack2(fA1.z, fA1.w);
            fpA[4] = pack2(fA2.x, fA2.y);
            fpB[0] = pack2(fB0.x, fB0.y); fpB[1] = pack2(fB0.z, fB0.w);
            fpB[2] = pack2(fB1.x, fB1.y); fpB[3] = pack2(fB1.z, fB1.w);
            fpB[4] = pack2(fB2.x, fB2.y);
            float evhA[2] = {evA.x, evA.y};
            float evhB[2] = {evB.x, evB.y};
#pragma unroll
            for (int h = 0; h < 2; h++) {
                float valA = evhA[h] + erh[h];
                valA = (valA >= 0.f) ? valA : NEG * valA;
                float valB = evhB[h] + erh[h];
                valB = (valB >= 0.f) ? valB : NEG * valB;
                float wA = __expf(valA);     // |val| small: max-free softmax exact
                float wB = __expf(valB);
                Z[h] += wA + wB;
                unsigned long long wpA = pack2(wA, wA);
                unsigned long long wpB = pack2(wB, wB);
#pragma unroll
                for (int tp = 0; tp < 5; tp++) {
                    fma2(acc[h][tp], fpA[tp], wpA);
                    fma2(acc[h][tp], fpB[tp], wpB);
                }
            }
        }
        if (k < cnt) {
            int s = __shfl_sync(0xffffffffu, myS, k);
            size_t sb = (size_t)s * BB + b;
            float2 ev = *(const float2*)&elb[sb * HH + 2 * hp];
            const float4* fb = (const float4*)(featb + sb * FP);
            float4 f0 = fb[0], f1 = fb[1], f2 = fb[2];
            unsigned long long fp[5];
            fp[0] = pack2(f0.x, f0.y); fp[1] = pack2(f0.z, f0.w);
            fp[2] = pack2(f1.x, f1.y); fp[3] = pack2(f1.z, f1.w);
            fp[4] = pack2(f2.x, f2.y);
            float evh[2] = {ev.x, ev.y};
#pragma unroll
            for (int h = 0; h < 2; h++) {
                float val = evh[h] + erh[h];
                val = (val >= 0.f) ? val : NEG * val;
                float wh = __expf(val);
                Z[h] += wh;
                unsigned long long wp = pack2(wh, wh);
#pragma unroll
                for (int tp = 0; tp < 5; tp++) fma2(acc[h][tp], fp[tp], wp);
            }
        }
    }

    __syncthreads();   // sWp writes ordered before epilogue reads

    // epilogue: W matvec for this warp's 2 heads
    float outd[DD];
#pragma unroll
    for (int d = 0; d < DD; d++) outd[d] = 0.f;
#pragma unroll
    for (int h = 0; h < 2; h++) {
        int gh = 2 * hp + h;
        float inv = (deg > 0) ? (0.25f / Z[h]) : 0.f;
#pragma unroll
        for (int d = 0; d < DD; d++) {
            unsigned long long o2 = 0ull;
#pragma unroll
            for (int tp = 0; tp < 5; tp++) fma2(o2, acc[h][tp], sWp[(gh * DD + d) * 5 + tp]);
            float ox, oy; unpack2(o2, ox, oy);
            float o = (ox + oy) * inv;   // leaky(x)*0.25 == leaky(x*0.25)
            o = (o >= 0.f) ? o : NEG * o;
            outd[d] += o;
        }
    }

    // combine the two head-pairs
    if (hp == 1) {
#pragma unroll
        for (int d = 0; d < DD; d++) spart[dslot][d][b] = outd[d];
    }
    __syncthreads();
    if (hp == 0) {
        float ls = 0.f, lss = 0.f;
        float* gout = g_g[v];
#pragma unroll
        for (int d = 0; d < DD; d++) {
            float s4 = outd[d] + spart[dslot][d][b];
            gout[((size_t)dst * DD + d) * BB + b] = s4;
            ls += s4; lss += s4 * s4;
        }
        if (stage == 0) {
#pragma unroll
            for (int off = 16; off; off >>= 1) {
                ls += __shfl_down_sync(0xffffffffu, ls, off);
                lss += __shfl_down_sync(0xffffffffu, lss, off);
            }
            if (b == 0) {
                atomicAdd(&g_stats2[v][0][dst & 255], (double)ls);
                atomicAdd(&g_stats2[v][1][dst & 255], (double)lss);
            }
        }
    }
}

// ---------------- reduce bucketed stats ----------------
__global__ void reduce_stats_kernel() {
    int w = threadIdx.x >> 5;
    int lane = threadIdx.x & 31;
    int slot = w >> 1, j = w & 1;
    double s = 0.0;
    for (int i = lane; i < 256; i += 32) s += g_stats2[slot][j][i];
#pragma unroll
    for (int off = 16; off; off >>= 1) s += __shfl_down_sync(0xffffffffu, s, off);
    if (lane == 0) g_stats[slot][j] = s;
}

// ---------------- final combine (rm/rs precomputed) ----------------
__global__ void final_kernel(float* __restrict__ out) {
    int i = blockIdx.x * blockDim.x + threadIdx.x;
    if (i >= NN * BB) return;
    int b = i & 31;
    int n = i >> 5;
    float rm = g_rm[0][i];
    float rs = g_rm[1][i];
    const float third = 1.f / 3.f;
#pragma unroll
    for (int d = 0; d < DD; d++) {
        size_t gi = ((size_t)n * DD + d) * BB + b;
        float v0 = (rm + g_g[0][gi] + g_g[1][gi]) * third;
        float v1 = (rs + g_g[2][gi] + g_g[3][gi]) * third;
        size_t o = ((size_t)n * BB + b) * DD + d;
        out[o] = v0;
        out[(size_t)NN * BB * DD + o] = v1;
    }
}

// ---------------- host orchestration ----------------
extern "C" void kernel_launch(void* const* d_in, const int* in_sizes, int n_in,
                              void* d_out, int out_size) {
    const float* xp;
    const int *ps_s, *ps_d, *rl_s, *rl_d;
    const float* prm[12];
    const float *rmw, *rmb, *rsw, *rsb;

    if (in_sizes[1] == EE) {
        xp = (const float*)d_in[0];
        ps_s = (const int*)d_in[1]; ps_d = (const int*)d_in[2];
        rl_s = (const int*)d_in[3]; rl_d = (const int*)d_in[4];
        for (int i = 0; i < 12; i++) prm[i] = (const float*)d_in[5 + i];
        rmw = (const float*)d_in[17]; rmb = (const float*)d_in[18];
        rsw = (const float*)d_in[19]; rsb = (const float*)d_in[20];
    } else {
        xp = (const float*)d_in[0];
        for (int i = 0; i < 12; i++) prm[i] = (const float*)d_in[1 + i];
        rmw = (const float*)d_in[13]; rmb = (const float*)d_in[14];
        rsw = (const float*)d_in[15]; rsb = (const float*)d_in[16];
        ps_s = (const int*)d_in[17]; ps_d = (const int*)d_in[18];
        rl_s = (const int*)d_in[19]; rl_d = (const int*)d_in[20];
    }

    float* out = (float*)d_out;

    const int s2_grp[4] = {0, 2, 1, 3};
    PP pp;
    Params p1, p2;
    for (int v = 0; v < 4; v++) {
        pp.fc[0][v] = prm[v * 3 + 0];
        pp.al[0][v] = prm[v * 3 + 1];
        pp.ar[0][v] = prm[v * 3 + 2];
        pp.fc[1][v] = prm[s2_grp[v] * 3 + 0] + HH * DD * TT;
        pp.al[1][v] = prm[s2_grp[v] * 3 + 1] + HH * DD;
        pp.ar[1][v] = prm[s2_grp[v] * 3 + 2] + HH * DD;
        p1.fc[v] = pp.fc[0][v];
        p2.fc[v] = pp.fc[1][v];
    }

    zero_kernel<<<(2 * NN + 320 + 255) / 256, 256>>>(pp);
    count_kernel<<<(EE + 255) / 256, 256>>>(ps_d, rl_d);
    scan_kernel<<<2, 1024>>>();
    fill_kernel<<<(EE + 255) / 256, 256>>>(ps_s, ps_d, rl_s, rl_d);

    prep_kernel<<<NN, 128>>>(xp, 0, rmw, rmb, rsw, rsb);
    gat4_kernel<<<dim3(NN / 4, 4), 256>>>(0, p1);
    reduce_stats_kernel<<<1, 256>>>();

    prep_kernel<<<NN, 128>>>(xp, 1, rmw, rmb, rsw, rsb);
    gat4_kernel<<<dim3(NN / 4, 4), 256>>>(1, p2);

    final_kernel<<<(NN * BB + 255) / 256, 256>>>(out);
}

// round 10
// speedup vs baseline: 1.0144x; 1.0144x over previous
#include <cuda_runtime.h>
#include <cstdint>

#define NN 10000
#define BB 32
#define EE 40000
#define HH 4
#define DD 10
#define TT 10
#define FP 12      // padded feat row (floats)
#define NEG 0.2f

// ---------------- scratch (zero-initialized at load; every call restores zeros) ----------------
__device__ float  g_feat[2][(size_t)NN * BB * FP];   // fp32 feats (N,B,12), 2 ch
__device__ float  g_el[4][(size_t)NN * BB * HH];     // (N,B,H) float4-friendly
__device__ float  g_er[4][(size_t)NN * BB * HH];
__device__ float  g_g[4][(size_t)NN * DD * BB];      // (N,D,B)
__device__ float  g_rm[2][(size_t)NN * BB];          // regression heads (mu, sg)
__device__ double g_stats2[4][2][256];               // bucketed LN stats (restored to 0)
__device__ double g_stats[4][2];
__device__ int    g_deg[2][NN];                      // restored to 0 by scan
__device__ int    g_rowstart[2][NN + 1];
__device__ int    g_cursor[2][NN];
__device__ int    g_csrc[2][EE];

struct Params { const float* fc[4]; };
struct PP { const float* fc[2][4]; const float* al[2][4]; const float* ar[2][4]; };

// ---------------- f32x2 helpers ----------------
__device__ __forceinline__ void fma2(unsigned long long& d, unsigned long long a, unsigned long long b) {
    asm("fma.rn.f32x2 %0, %1, %2, %0;" : "+l"(d) : "l"(a), "l"(b));
}
__device__ __forceinline__ unsigned long long pack2(float x, float y) {
    unsigned long long r; asm("mov.b64 %0, {%1, %2};" : "=l"(r) : "f"(x), "f"(y)); return r;
}
__device__ __forceinline__ void unpack2(unsigned long long v, float& x, float& y) {
    asm("mov.b64 {%0, %1}, %2;" : "=f"(x), "=f"(y) : "l"(v));
}

__global__ void count_kernel(const int* __restrict__ ps_dst, const int* __restrict__ rl_dst) {
    int e = blockIdx.x * blockDim.x + threadIdx.x;
    if (e >= EE) return;
    atomicAdd(&g_deg[0][ps_dst[e]], 1);
    atomicAdd(&g_deg[1][rl_dst[e]], 1);
}

// 2 blocks (one per graph); restores g_deg to zero for the next call
__global__ void scan_kernel() {
    __shared__ int sh[1024];
    int t = threadIdx.x;
    int g = blockIdx.x;
    const int CH = 10;
    int base = t * CH;
    int loc[CH];
    int s = 0;
#pragma unroll
    for (int i = 0; i < CH; i++) {
        int idx = base + i;
        int v = 0;
        if (idx < NN) { v = g_deg[g][idx]; g_deg[g][idx] = 0; }   // read + restore
        loc[i] = s; s += v;
    }
    sh[t] = s;
    __syncthreads();
    for (int off = 1; off < 1024; off <<= 1) {
        int v = (t >= off) ? sh[t - off] : 0;
        __syncthreads();
        sh[t] += v;
        __syncthreads();
    }
    int excl = (t > 0) ? sh[t - 1] : 0;
#pragma unroll
    for (int i = 0; i < CH; i++) {
        int idx = base + i;
        if (idx < NN) {
            int rs = excl + loc[i];
            g_rowstart[g][idx] = rs;
            g_cursor[g][idx] = rs;
        }
    }
    if (t == 1023) g_rowstart[g][NN] = sh[1023];
}

__global__ void fill_kernel(const int* __restrict__ ps_src, const int* __restrict__ ps_dst,
                            const int* __restrict__ rl_src, const int* __restrict__ rl_dst) {
    int e = blockIdx.x * blockDim.x + threadIdx.x;
    if (e >= EE) return;
    int p = atomicAdd(&g_cursor[0][ps_dst[e]], 1);
    g_csrc[0][p] = ps_src[e];
    p = atomicAdd(&g_cursor[1][rl_dst[e]], 1);
    g_csrc[1][p] = rl_src[e];
}

// ---------------- prep: feats fp32 (N,B,12) + el/er float4 (N,B,H); stage0 also rm/rs ----------------
// u_l = W^T a_l, u_r = W^T a_r computed in-block (tiny; removes a dependency launch)
__global__ void __launch_bounds__(128) prep_kernel(const float* __restrict__ x, int stage, PP pp,
                                                   const float* __restrict__ wmu, const float* __restrict__ bmu,
                                                   const float* __restrict__ wsg, const float* __restrict__ bsg) {
    __shared__ float sx[TT][BB * 3];
    __shared__ float sf[2][TT][BB];
    __shared__ float sul[4][HH][TT], sur[4][HH][TT];
    __shared__ float smean[4], srstd[4];
    __shared__ float swm[TT], sws[TT], sb[2];
    int n = blockIdx.x;
    int tid = threadIdx.x;
    int b = tid & 31, vv = tid >> 5;

    for (int i = tid; i < 4 * HH * TT; i += 128) {
        int t = i % TT, hh = (i / TT) % HH, v = i / (TT * HH);
        const float* fcp = pp.fc[stage][v];
        const float* alp = pp.al[stage][v];
        const float* arp = pp.ar[stage][v];
        float ul = 0.f, ur = 0.f;
#pragma unroll
        for (int d = 0; d < DD; d++) {
            float wv = fcp[(hh * DD + d) * TT + t];
            ul += alp[hh * DD + d] * wv;
            ur += arp[hh * DD + d] * wv;
        }
        sul[v][hh][t] = ul;
        sur[v][hh][t] = ur;
    }
    if (stage == 0) {
        if (tid < TT) { swm[tid] = wmu[tid]; sws[tid] = wsg[tid]; }
        if (tid == 10) sb[0] = bmu[0];
        if (tid == 11) sb[1] = bsg[0];
        for (int i = tid; i < TT * 96; i += 128) {
            int t = i / 96, j = i % 96;
            sx[t][j] = x[((size_t)t * NN + n) * 96 + j];
        }
        __syncthreads();
        for (int i = tid; i < 2 * TT * BB; i += 128) {
            int ch = i / (TT * BB), r = i % (TT * BB), t = r / BB, bb = r % BB;
            sf[ch][t][bb] = sx[t][bb * 3 + ch];
        }
        __syncthreads();
        if (vv == 2) {
            float a = sb[0];
#pragma unroll
            for (int t = 0; t < TT; t++) a += sf[0][t][b] * swm[t];
            g_rm[0][(size_t)n * BB + b] = a;
        } else if (vv == 3) {
            float a = sb[1];
#pragma unroll
            for (int t = 0; t < TT; t++) a += sf[1][t][b] * sws[t];
            g_rm[1][(size_t)n * BB + b] = a;
        }
    } else {
        if (tid < 4) {
            const double invn = 1.0 / ((double)NN * DD * BB);
            double mean = g_stats[tid][0] * invn;
            double var = g_stats[tid][1] * invn - mean * mean;
            smean[tid] = (float)mean;
            srstd[tid] = (float)rsqrt(var + 1e-5);
        }
        __syncthreads();
        for (int i = tid; i < TT * BB; i += 128) {
            int t = i / BB, bb = i % BB;
            size_t gi = ((size_t)n * DD + t) * BB + bb;
            float v0 = (g_g[0][gi] - smean[0]) * srstd[0];
            float v1 = (g_g[1][gi] - smean[1]) * srstd[1];
            float v2 = (g_g[2][gi] - smean[2]) * srstd[2];
            float v3 = (g_g[3][gi] - smean[3]) * srstd[3];
            sf[0][t][bb] = 0.5f * (v0 + v1);
            sf[1][t][bb] = 0.5f * (v2 + v3);
        }
        __syncthreads();
    }

    if (vv < 2) {
        float4* dstp = (float4*)&g_feat[vv][((size_t)n * BB + b) * FP];
        dstp[0] = make_float4(sf[vv][0][b], sf[vv][1][b], sf[vv][2][b], sf[vv][3][b]);
        dstp[1] = make_float4(sf[vv][4][b], sf[vv][5][b], sf[vv][6][b], sf[vv][7][b]);
        dstp[2] = make_float4(sf[vv][8][b], sf[vv][9][b], 0.f, 0.f);
    }

    int ch = vv & 1;
    float f[TT];
#pragma unroll
    for (int t = 0; t < TT; t++) f[t] = sf[ch][t][b];
    float elh[HH], erh[HH];
#pragma unroll
    for (int h = 0; h < HH; h++) {
        float a = 0.f, c = 0.f;
#pragma unroll
        for (int t = 0; t < TT; t++) { a += sul[vv][h][t] * f[t]; c += sur[vv][h][t] * f[t]; }
        elh[h] = a; erh[h] = c;
    }
    *(float4*)&g_el[vv][((size_t)n * BB + b) * HH] = make_float4(elh[0], elh[1], elh[2], elh[3]);
    *(float4*)&g_er[vv][((size_t)n * BB + b) * HH] = make_float4(erh[0], erh[1], erh[2], erh[3]);
}

// ---------------- GAT: one warp per (dst, variant), 4-edge load batching ----------------
__global__ void __launch_bounds__(128) gat4_kernel(int stage, Params p) {
    __shared__ unsigned long long sWp[HH * DD * 5];
    int v = blockIdx.y;
    int graph = stage ? (v & 1) : (v >> 1);
    int tid = threadIdx.x;
    int b = tid & 31, w = tid >> 5;
    int dst = blockIdx.x * 4 + w;

    int s0 = g_rowstart[graph][dst];
    int deg = g_rowstart[graph][dst + 1] - s0;
    float4 e4 = *(const float4*)&g_er[v][((size_t)dst * BB + b) * HH];

    for (int i = tid; i < HH * DD * 5; i += 128) {
        int row = i / 5, tp = i % 5;
        sWp[i] = pack2(p.fc[v][row * TT + 2 * tp], p.fc[v][row * TT + 2 * tp + 1]);
    }

    float erh[HH] = {e4.x, e4.y, e4.z, e4.w};
    const float4* el4 = (const float4*)g_el[v];
    const float* featb = g_feat[v & 1];
    const int* csrcp = g_csrc[graph];

    unsigned long long acc[HH][5];
    float Z[HH];
#pragma unroll
    for (int h = 0; h < HH; h++) {
        Z[h] = 0.f;
#pragma unroll
        for (int t = 0; t < 5; t++) acc[h][t] = 0ull;
    }

    for (int base = 0; base < deg; base += 32) {
        int cnt = min(32, deg - base);
        int myS = (b < cnt) ? csrcp[s0 + base + b] : 0;
        int k = 0;
        // 4-edge batch: 16 loads in flight behind one latency exposure
        for (; k + 3 < cnt; k += 4) {
            int sj[4];
#pragma unroll
            for (int j = 0; j < 4; j++) sj[j] = __shfl_sync(0xffffffffu, myS, k + j);
            float4 ev[4], f0[4], f1[4], f2[4];
#pragma unroll
            for (int j = 0; j < 4; j++) {
                size_t sb = (size_t)sj[j] * BB + b;
                ev[j] = el4[sb];
                const float4* fb = (const float4*)(featb + sb * FP);
                f0[j] = fb[0]; f1[j] = fb[1]; f2[j] = fb[2];
            }
#pragma unroll
            for (int j = 0; j < 4; j++) {
                unsigned long long fp[5];
                fp[0] = pack2(f0[j].x, f0[j].y); fp[1] = pack2(f0[j].z, f0[j].w);
                fp[2] = pack2(f1[j].x, f1[j].y); fp[3] = pack2(f1[j].z, f1[j].w);
                fp[4] = pack2(f2[j].x, f2[j].y);
                float evh[HH] = {ev[j].x, ev[j].y, ev[j].z, ev[j].w};
#pragma unroll
                for (int h = 0; h < HH; h++) {
                    float val = evh[h] + erh[h];
                    val = (val >= 0.f) ? val : NEG * val;
                    float wh = __expf(val);          // |val| small: max-free softmax exact
                    Z[h] += wh;
                    unsigned long long wp = pack2(wh, wh);
#pragma unroll
                    for (int tp = 0; tp < 5; tp++) fma2(acc[h][tp], fp[tp], wp);
                }
            }
        }
        // 2-edge tail
        for (; k + 1 < cnt; k += 2) {
            int sA = __shfl_sync(0xffffffffu, myS, k);
            int sB = __shfl_sync(0xffffffffu, myS, k + 1);
            size_t sbA = (size_t)sA * BB + b;
            size_t sbB = (size_t)sB * BB + b;
            float4 evA = el4[sbA];
            float4 evB = el4[sbB];
            const float4* fbA = (const float4*)(featb + sbA * FP);
            const float4* fbB = (const float4*)(featb + sbB * FP);
            float4 fA0 = fbA[0], fA1 = fbA[1], fA2 = fbA[2];
            float4 fB0 = fbB[0], fB1 = fbB[1], fB2 = fbB[2];
            unsigned long long fpA[5], fpB[5];
            fpA[0] = pack2(fA0.x, fA0.y); fpA[1] = pack2(fA0.z, fA0.w);
            fpA[2] = pack2(fA1.x, fA1.y); fpA[3] = pack2(fA1.z, fA1.w);
            fpA[4] = pack2(fA2.x, fA2.y);
            fpB[0] = pack2(fB0.x, fB0.y); fpB[1] = pack2(fB0.z, fB0.w);
            fpB[2] = pack2(fB1.x, fB1.y); fpB[3] = pack2(fB1.z, fB1.w);
            fpB[4] = pack2(fB2.x, fB2.y);
            float evhA[HH] = {evA.x, evA.y, evA.z, evA.w};
            float evhB[HH] = {evB.x, evB.y, evB.z, evB.w};
#pragma unroll
            for (int h = 0; h < HH; h++) {
                float valA = evhA[h] + erh[h];
                valA = (valA >= 0.f) ? valA : NEG * valA;
                float valB = evhB[h] + erh[h];
                valB = (valB >= 0.f) ? valB : NEG * valB;
                float wA = __expf(valA);
                float wB = __expf(valB);
                Z[h] += wA + wB;
                unsigned long long wpA = pack2(wA, wA);
                unsigned long long wpB = pack2(wB, wB);
#pragma unroll
                for (int tp = 0; tp < 5; tp++) {
                    fma2(acc[h][tp], fpA[tp], wpA);
                    fma2(acc[h][tp], fpB[tp], wpB);
                }
            }
        }
        if (k < cnt) {
            int s = __shfl_sync(0xffffffffu, myS, k);
            size_t sb = (size_t)s * BB + b;
            float4 ev = el4[sb];
            const float4* fb = (const float4*)(featb + sb * FP);
            float4 f0 = fb[0], f1 = fb[1], f2 = fb[2];
            unsigned long long fp[5];
            fp[0] = pack2(f0.x, f0.y); fp[1] = pack2(f0.z, f0.w);
            fp[2] = pack2(f1.x, f1.y); fp[3] = pack2(f1.z, f1.w);
            fp[4] = pack2(f2.x, f2.y);
            float evh[HH] = {ev.x, ev.y, ev.z, ev.w};
#pragma unroll
            for (int h = 0; h < HH; h++) {
                float val = evh[h] + erh[h];
                val = (val >= 0.f) ? val : NEG * val;
                float wh = __expf(val);
                Z[h] += wh;
                unsigned long long wp = pack2(wh, wh);
#pragma unroll
                for (int tp = 0; tp < 5; tp++) fma2(acc[h][tp], fp[tp], wp);
            }
        }
    }

    __syncthreads();   // sWp writes ordered before epilogue reads (off the startup path)

    float outd[DD];
#pragma unroll
    for (int d = 0; d < DD; d++) outd[d] = 0.f;
#pragma unroll
    for (int h = 0; h < HH; h++) {
        float inv = (deg > 0) ? (0.25f / Z[h]) : 0.f;
#pragma unroll
        for (int d = 0; d < DD; d++) {
            unsigned long long o2 = 0ull;
#pragma unroll
            for (int tp = 0; tp < 5; tp++) fma2(o2, acc[h][tp], sWp[(h * DD + d) * 5 + tp]);
            float ox, oy; unpack2(o2, ox, oy);
            float o = (ox + oy) * inv;   // leaky(x)*0.25 == leaky(x*0.25)
            o = (o >= 0.f) ? o : NEG * o;
            outd[d] += o;
        }
    }

    float ls = 0.f, lss = 0.f;
    float* gout = g_g[v];
#pragma unroll
    for (int d = 0; d < DD; d++) {
        gout[((size_t)dst * DD + d) * BB + b] = outd[d];
        ls += outd[d]; lss += outd[d] * outd[d];
    }
    if (stage == 0) {
#pragma unroll
        for (int off = 16; off; off >>= 1) {
            ls += __shfl_down_sync(0xffffffffu, ls, off);
            lss += __shfl_down_sync(0xffffffffu, lss, off);
        }
        if (b == 0) {
            atomicAdd(&g_stats2[v][0][dst & 255], (double)ls);
            atomicAdd(&g_stats2[v][1][dst & 255], (double)lss);
        }
    }
}

// ---------------- reduce bucketed stats; restores g_stats2 to zero ----------------
__global__ void reduce_stats_kernel() {
    int w = threadIdx.x >> 5;
    int lane = threadIdx.x & 31;
    int slot = w >> 1, j = w & 1;
    double s = 0.0;
    for (int i = lane; i < 256; i += 32) {
        s += g_stats2[slot][j][i];
        g_stats2[slot][j][i] = 0.0;      // restore for next call
    }
#pragma unroll
    for (int off = 16; off; off >>= 1) s += __shfl_down_sync(0xffffffffu, s, off);
    if (lane == 0) g_stats[slot][j] = s;
}

// ---------------- final combine (rm/rs precomputed) ----------------
__global__ void final_kernel(float* __restrict__ out) {
    int i = blockIdx.x * blockDim.x + threadIdx.x;
    if (i >= NN * BB) return;
    int b = i & 31;
    int n = i >> 5;
    float rm = g_rm[0][i];
    float rs = g_rm[1][i];
    const float third = 1.f / 3.f;
#pragma unroll
    for (int d = 0; d < DD; d++) {
        size_t gi = ((size_t)n * DD + d) * BB + b;
        float v0 = (rm + g_g[0][gi] + g_g[1][gi]) * third;
        float v1 = (rs + g_g[2][gi] + g_g[3][gi]) * third;
        size_t o = ((size_t)n * BB + b) * DD + d;
        out[o] = v0;
        out[(size_t)NN * BB * DD + o] = v1;
    }
}

// ---------------- host orchestration ----------------
extern "C" void kernel_launch(void* const* d_in, const int* in_sizes, int n_in,
                              void* d_out, int out_size) {
    const float* xp;
    const int *ps_s, *ps_d, *rl_s, *rl_d;
    const float* prm[12];
    const float *rmw, *rmb, *rsw, *rsb;

    if (in_sizes[1] == EE) {
        xp = (const float*)d_in[0];
        ps_s = (const int*)d_in[1]; ps_d = (const int*)d_in[2];
        rl_s = (const int*)d_in[3]; rl_d = (const int*)d_in[4];
        for (int i = 0; i < 12; i++) prm[i] = (const float*)d_in[5 + i];
        rmw = (const float*)d_in[17]; rmb = (const float*)d_in[18];
        rsw = (const float*)d_in[19]; rsb = (const float*)d_in[20];
    } else {
        xp = (const float*)d_in[0];
        for (int i = 0; i < 12; i++) prm[i] = (const float*)d_in[1 + i];
        rmw = (const float*)d_in[13]; rmb = (const float*)d_in[14];
        rsw = (const float*)d_in[15]; rsb = (const float*)d_in[16];
        ps_s = (const int*)d_in[17]; ps_d = (const int*)d_in[18];
        rl_s = (const int*)d_in[19]; rl_d = (const int*)d_in[20];
    }

    float* out = (float*)d_out;

    const int s2_grp[4] = {0, 2, 1, 3};
    PP pp;
    Params p1, p2;
    for (int v = 0; v < 4; v++) {
        pp.fc[0][v] = prm[v * 3 + 0];
        pp.al[0][v] = prm[v * 3 + 1];
        pp.ar[0][v] = prm[v * 3 + 2];
        pp.fc[1][v] = prm[s2_grp[v] * 3 + 0] + HH * DD * TT;
        pp.al[1][v] = prm[s2_grp[v] * 3 + 1] + HH * DD;
        pp.ar[1][v] = prm[s2_grp[v] * 3 + 2] + HH * DD;
        p1.fc[v] = pp.fc[0][v];
        p2.fc[v] = pp.fc[1][v];
    }

    count_kernel<<<(EE + 255) / 256, 256>>>(ps_d, rl_d);
    scan_kernel<<<2, 1024>>>();
    fill_kernel<<<(EE + 255) / 256, 256>>>(ps_s, ps_d, rl_s, rl_d);

    prep_kernel<<<NN, 128>>>(xp, 0, pp, rmw, rmb, rsw, rsb);
    gat4_kernel<<<dim3(NN / 4, 4), 128>>>(0, p1);
    reduce_stats_kernel<<<1, 256>>>();

    prep_kernel<<<NN, 128>>>(xp, 1, pp, rmw, rmb, rsw, rsb);
    gat4_kernel<<<dim3(NN / 4, 4), 128>>>(1, p2);

    final_kernel<<<(NN * BB + 255) / 256, 256>>>(out);
}

// round 11
// speedup vs baseline: 1.0637x; 1.0486x over previous
#include <cuda_runtime.h>
#include <cstdint>

#define NN 10000
#define BB 32
#define EE 40000
#define HH 4
#define DD 10
#define TT 10
#define FP 12      // padded feat row (floats)
#define NEG 0.2f

// ---------------- scratch (zero-initialized at load; every call restores zeros) ----------------
__device__ float  g_feat[2][(size_t)NN * BB * FP];   // fp32 feats (N,B,12), 2 ch
__device__ float  g_el[4][(size_t)NN * BB * HH];     // (N,B,H) float4-friendly
__device__ float  g_er[4][(size_t)NN * BB * HH];
__device__ float  g_g[4][(size_t)NN * DD * BB];      // (N,D,B)
__device__ float  g_rm[2][(size_t)NN * BB];          // regression heads (mu, sg)
__device__ float  g_ul[2][4][HH][TT];
__device__ float  g_ur[2][4][HH][TT];
__device__ double g_stats2[4][2][256];               // bucketed LN stats (restored to 0)
__device__ double g_stats[4][2];
__device__ int    g_deg[2][NN];                      // restored to 0 by scan
__device__ int    g_rowstart[2][NN + 1];
__device__ int    g_cursor[2][NN];
__device__ int    g_csrc[2][EE];

struct Params { const float* fc[4]; };
struct PP { const float* fc[2][4]; const float* al[2][4]; const float* ar[2][4]; };

// ---------------- f32x2 helpers ----------------
__device__ __forceinline__ void fma2(unsigned long long& d, unsigned long long a, unsigned long long b) {
    asm("fma.rn.f32x2 %0, %1, %2, %0;" : "+l"(d) : "l"(a), "l"(b));
}
__device__ __forceinline__ unsigned long long pack2(float x, float y) {
    unsigned long long r; asm("mov.b64 %0, {%1, %2};" : "=l"(r) : "f"(x), "f"(y)); return r;
}
__device__ __forceinline__ void unpack2(unsigned long long v, float& x, float& y) {
    asm("mov.b64 {%0, %1}, %2;" : "=f"(x), "=f"(y) : "l"(v));
}

// ---------------- count degrees; last block computes u = W^T a ----------------
__global__ void count_kernel(const int* __restrict__ ps_dst, const int* __restrict__ rl_dst, PP p) {
    int tid = threadIdx.x;
    if (blockIdx.x == gridDim.x - 1) {
        for (int j = tid; j < 2 * 4 * HH * TT; j += 256) {
            int t = j % TT;
            int h = (j / TT) % HH;
            int v = (j / (TT * HH)) % 4;
            int s = j / (TT * HH * 4);
            float ul = 0.f, ur = 0.f;
#pragma unroll
            for (int d = 0; d < DD; d++) {
                float w = p.fc[s][v][(h * DD + d) * TT + t];
                ul += p.al[s][v][h * DD + d] * w;
                ur += p.ar[s][v][h * DD + d] * w;
            }
            g_ul[s][v][h][t] = ul;
            g_ur[s][v][h][t] = ur;
        }
        return;
    }
    int e = blockIdx.x * blockDim.x + tid;
    if (e >= EE) return;
    atomicAdd(&g_deg[0][ps_dst[e]], 1);
    atomicAdd(&g_deg[1][rl_dst[e]], 1);
}

// 2 blocks (one per graph); restores g_deg to zero for the next call
__global__ void scan_kernel() {
    __shared__ int sh[1024];
    int t = threadIdx.x;
    int g = blockIdx.x;
    const int CH = 10;
    int base = t * CH;
    int loc[CH];
    int s = 0;
#pragma unroll
    for (int i = 0; i < CH; i++) {
        int idx = base + i;
        int v = 0;
        if (idx < NN) { v = g_deg[g][idx]; g_deg[g][idx] = 0; }   // read + restore
        loc[i] = s; s += v;
    }
    sh[t] = s;
    __syncthreads();
    for (int off = 1; off < 1024; off <<= 1) {
        int v = (t >= off) ? sh[t - off] : 0;
        __syncthreads();
        sh[t] += v;
        __syncthreads();
    }
    int excl = (t > 0) ? sh[t - 1] : 0;
#pragma unroll
    for (int i = 0; i < CH; i++) {
        int idx = base + i;
        if (idx < NN) {
            int rs = excl + loc[i];
            g_rowstart[g][idx] = rs;
            g_cursor[g][idx] = rs;
        }
    }
    if (t == 1023) g_rowstart[g][NN] = sh[1023];
}

__global__ void fill_kernel(const int* __restrict__ ps_src, const int* __restrict__ ps_dst,
                            const int* __restrict__ rl_src, const int* __restrict__ rl_dst) {
    int e = blockIdx.x * blockDim.x + threadIdx.x;
    if (e >= EE) return;
    int p = atomicAdd(&g_cursor[0][ps_dst[e]], 1);
    g_csrc[0][p] = ps_src[e];
    p = atomicAdd(&g_cursor[1][rl_dst[e]], 1);
    g_csrc[1][p] = rl_src[e];
}

// ---------------- prep: feats fp32 (N,B,12) + el/er float4 (N,B,H); stage0 also rm/rs ----------------
// stage 0 reads sx directly (stride-3 LDS, conflict-free) — no transpose pass
__global__ void __launch_bounds__(128) prep_kernel(const float* __restrict__ x, int stage,
                                                   const float* __restrict__ wmu, const float* __restrict__ bmu,
                                                   const float* __restrict__ wsg, const float* __restrict__ bsg) {
    __shared__ float sx[TT][BB * 3];
    __shared__ float sf[2][TT][BB];
    __shared__ float sul[4][HH][TT], sur[4][HH][TT];
    __shared__ float smean[4], srstd[4];
    __shared__ float swm[TT], sws[TT], sb[2];
    int n = blockIdx.x;
    int tid = threadIdx.x;
    int b = tid & 31, vv = tid >> 5;

    for (int i = tid; i < 4 * HH * TT; i += 128) {
        int t = i % TT, hh = (i / TT) % HH, v = i / (TT * HH);
        sul[v][hh][t] = g_ul[stage][v][hh][t];
        sur[v][hh][t] = g_ur[stage][v][hh][t];
    }
    if (stage == 0) {
        if (tid < TT) { swm[tid] = wmu[tid]; sws[tid] = wsg[tid]; }
        if (tid == 10) sb[0] = bmu[0];
        if (tid == 11) sb[1] = bsg[0];
        for (int i = tid; i < TT * 96; i += 128) {
            int t = i / 96, j = i % 96;
            sx[t][j] = x[((size_t)t * NN + n) * 96 + j];
        }
        __syncthreads();
        if (vv == 2) {
            float a = sb[0];
#pragma unroll
            for (int t = 0; t < TT; t++) a += sx[t][b * 3] * swm[t];
            g_rm[0][(size_t)n * BB + b] = a;
        } else if (vv == 3) {
            float a = sb[1];
#pragma unroll
            for (int t = 0; t < TT; t++) a += sx[t][b * 3 + 1] * sws[t];
            g_rm[1][(size_t)n * BB + b] = a;
        }
    } else {
        if (tid < 4) {
            const double invn = 1.0 / ((double)NN * DD * BB);
            double mean = g_stats[tid][0] * invn;
            double var = g_stats[tid][1] * invn - mean * mean;
            smean[tid] = (float)mean;
            srstd[tid] = (float)rsqrt(var + 1e-5);
        }
        __syncthreads();
        for (int i = tid; i < TT * BB; i += 128) {
            int t = i / BB, bb = i % BB;
            size_t gi = ((size_t)n * DD + t) * BB + bb;
            float v0 = (g_g[0][gi] - smean[0]) * srstd[0];
            float v1 = (g_g[1][gi] - smean[1]) * srstd[1];
            float v2 = (g_g[2][gi] - smean[2]) * srstd[2];
            float v3 = (g_g[3][gi] - smean[3]) * srstd[3];
            sf[0][t][bb] = 0.5f * (v0 + v1);
            sf[1][t][bb] = 0.5f * (v2 + v3);
        }
        __syncthreads();
    }

    // per-thread feature vector for channel ch = vv&1
    int ch = vv & 1;
    float f[TT];
    if (stage == 0) {
#pragma unroll
        for (int t = 0; t < TT; t++) f[t] = sx[t][b * 3 + ch];
    } else {
#pragma unroll
        for (int t = 0; t < TT; t++) f[t] = sf[ch][t][b];
    }

    // feat write (warps 0,1 == channels 0,1; f is exactly that channel)
    if (vv < 2) {
        float4* dstp = (float4*)&g_feat[vv][((size_t)n * BB + b) * FP];
        dstp[0] = make_float4(f[0], f[1], f[2], f[3]);
        dstp[1] = make_float4(f[4], f[5], f[6], f[7]);
        dstp[2] = make_float4(f[8], f[9], 0.f, 0.f);
    }

    float elh[HH], erh[HH];
#pragma unroll
    for (int h = 0; h < HH; h++) {
        float a = 0.f, c = 0.f;
#pragma unroll
        for (int t = 0; t < TT; t++) { a += sul[vv][h][t] * f[t]; c += sur[vv][h][t] * f[t]; }
        elh[h] = a; erh[h] = c;
    }
    *(float4*)&g_el[vv][((size_t)n * BB + b) * HH] = make_float4(elh[0], elh[1], elh[2], elh[3]);
    *(float4*)&g_er[vv][((size_t)n * BB + b) * HH] = make_float4(erh[0], erh[1], erh[2], erh[3]);
}

// ---------------- GAT: one warp per (dst, variant), all 4 heads, 2-edge pipelined ----------------
__global__ void __launch_bounds__(128) gat4_kernel(int stage, Params p) {
    __shared__ unsigned long long sWp[HH * DD * 5];
    int v = blockIdx.y;
    int graph = stage ? (v & 1) : (v >> 1);
    int tid = threadIdx.x;
    int b = tid & 31, w = tid >> 5;
    int dst = blockIdx.x * 4 + w;

    int s0 = g_rowstart[graph][dst];
    int deg = g_rowstart[graph][dst + 1] - s0;
    float4 e4 = *(const float4*)&g_er[v][((size_t)dst * BB + b) * HH];

    // stage W (ordered before epilogue by the post-mainloop barrier)
    for (int i = tid; i < HH * DD * 5; i += 128) {
        int row = i / 5, tp = i % 5;
        sWp[i] = pack2(p.fc[v][row * TT + 2 * tp], p.fc[v][row * TT + 2 * tp + 1]);
    }

    float erh[HH] = {e4.x, e4.y, e4.z, e4.w};
    const float4* el4 = (const float4*)g_el[v];
    const float* featb = g_feat[v & 1];

    unsigned long long acc[HH][5];
    float Z[HH];
#pragma unroll
    for (int h = 0; h < HH; h++) {
        Z[h] = 0.f;
#pragma unroll
        for (int t = 0; t < 5; t++) acc[h][t] = 0ull;
    }

    for (int base = 0; base < deg; base += 32) {
        int cnt = min(32, deg - base);
        int myS = (b < cnt) ? g_csrc[graph][s0 + base + b] : 0;
        int k = 0;
        for (; k + 1 < cnt; k += 2) {
            int sA = __shfl_sync(0xffffffffu, myS, k);
            int sB = __shfl_sync(0xffffffffu, myS, k + 1);
            size_t sbA = (size_t)sA * BB + b;
            size_t sbB = (size_t)sB * BB + b;
            float4 evA = el4[sbA];
            float4 evB = el4[sbB];
            const float4* fbA = (const float4*)(featb + sbA * FP);
            const float4* fbB = (const float4*)(featb + sbB * FP);
            float4 fA0 = fbA[0], fA1 = fbA[1], fA2 = fbA[2];
            float4 fB0 = fbB[0], fB1 = fbB[1], fB2 = fbB[2];

            unsigned long long fpA[5], fpB[5];
            fpA[0] = pack2(fA0.x, fA0.y); fpA[1] = pack2(fA0.z, fA0.w);
            fpA[2] = pack2(fA1.x, fA1.y); fpA[3] = pack2(fA1.z, fA1.w);
            fpA[4] = pack2(fA2.x, fA2.y);
            fpB[0] = pack2(fB0.x, fB0.y); fpB[1] = pack2(fB0.z, fB0.w);
            fpB[2] = pack2(fB1.x, fB1.y); fpB[3] = pack2(fB1.z, fB1.w);
            fpB[4] = pack2(fB2.x, fB2.y);
            float evhA[HH] = {evA.x, evA.y, evA.z, evA.w};
            float evhB[HH] = {evB.x, evB.y, evB.z, evB.w};
#pragma unroll
            for (int h = 0; h < HH; h++) {
                float valA = evhA[h] + erh[h];
                valA = (valA >= 0.f) ? valA : NEG * valA;
                float valB = evhB[h] + erh[h];
                valB = (valB >= 0.f) ? valB : NEG * valB;
                float wA = __expf(valA);     // |val| small: max-free softmax exact
                float wB = __expf(valB);
                Z[h] += wA + wB;
                unsigned long long wpA = pack2(wA, wA);
                unsigned long long wpB = pack2(wB, wB);
#pragma unroll
                for (int tp = 0; tp < 5; tp++) {
                    fma2(acc[h][tp], fpA[tp], wpA);
                    fma2(acc[h][tp], fpB[tp], wpB);
                }
            }
        }
        if (k < cnt) {
            int s = __shfl_sync(0xffffffffu, myS, k);
            size_t sb = (size_t)s * BB + b;
            float4 ev = el4[sb];
            const float4* fb = (const float4*)(featb + sb * FP);
            float4 f0 = fb[0], f1 = fb[1], f2 = fb[2];
            unsigned long long fp[5];
            fp[0] = pack2(f0.x, f0.y); fp[1] = pack2(f0.z, f0.w);
            fp[2] = pack2(f1.x, f1.y); fp[3] = pack2(f1.z, f1.w);
            fp[4] = pack2(f2.x, f2.y);
            float evh[HH] = {ev.x, ev.y, ev.z, ev.w};
#pragma unroll
            for (int h = 0; h < HH; h++) {
                float val = evh[h] + erh[h];
                val = (val >= 0.f) ? val : NEG * val;
                float wh = __expf(val);
                Z[h] += wh;
                unsigned long long wp = pack2(wh, wh);
#pragma unroll
                for (int tp = 0; tp < 5; tp++) fma2(acc[h][tp], fp[tp], wp);
            }
        }
    }

    __syncthreads();   // orders all sWp writes before epilogue reads (off the startup path)

    // epilogue: W matvec (packed) + leaky + head mean
    float outd[DD];
#pragma unroll
    for (int d = 0; d < DD; d++) outd[d] = 0.f;
#pragma unroll
    for (int h = 0; h < HH; h++) {
        float inv = (deg > 0) ? (0.25f / Z[h]) : 0.f;
#pragma unroll
        for (int d = 0; d < DD; d++) {
            unsigned long long o2 = 0ull;
#pragma unroll
            for (int tp = 0; tp < 5; tp++) fma2(o2, acc[h][tp], sWp[(h * DD + d) * 5 + tp]);
            float ox, oy; unpack2(o2, ox, oy);
            float o = (ox + oy) * inv;   // leaky(x)*0.25 == leaky(x*0.25)
            o = (o >= 0.f) ? o : NEG * o;
            outd[d] += o;
        }
    }

    float ls = 0.f, lss = 0.f;
    float* gout = g_g[v];
#pragma unroll
    for (int d = 0; d < DD; d++) {
        gout[((size_t)dst * DD + d) * BB + b] = outd[d];
        ls += outd[d]; lss += outd[d] * outd[d];
    }
    if (stage == 0) {
#pragma unroll
        for (int off = 16; off; off >>= 1) {
            ls += __shfl_down_sync(0xffffffffu, ls, off);
            lss += __shfl_down_sync(0xffffffffu, lss, off);
        }
        if (b == 0) {
            atomicAdd(&g_stats2[v][0][dst & 255], (double)ls);
            atomicAdd(&g_stats2[v][1][dst & 255], (double)lss);
        }
    }
}

// ---------------- reduce bucketed stats; restores g_stats2 to zero ----------------
__global__ void reduce_stats_kernel() {
    int w = threadIdx.x >> 5;
    int lane = threadIdx.x & 31;
    int slot = w >> 1, j = w & 1;
    double s = 0.0;
    for (int i = lane; i < 256; i += 32) {
        s += g_stats2[slot][j][i];
        g_stats2[slot][j][i] = 0.0;      // restore for next call
    }
#pragma unroll
    for (int off = 16; off; off >>= 1) s += __shfl_down_sync(0xffffffffu, s, off);
    if (lane == 0) g_stats[slot][j] = s;
}

// ---------------- final combine (rm/rs precomputed) ----------------
__global__ void final_kernel(float* __restrict__ out) {
    int i = blockIdx.x * blockDim.x + threadIdx.x;
    if (i >= NN * BB) return;
    int b = i & 31;
    int n = i >> 5;
    float rm = g_rm[0][i];
    float rs = g_rm[1][i];
    const float third = 1.f / 3.f;
#pragma unroll
    for (int d = 0; d < DD; d++) {
        size_t gi = ((size_t)n * DD + d) * BB + b;
        float v0 = (rm + g_g[0][gi] + g_g[1][gi]) * third;
        float v1 = (rs + g_g[2][gi] + g_g[3][gi]) * third;
        size_t o = ((size_t)n * BB + b) * DD + d;
        out[o] = v0;
        out[(size_t)NN * BB * DD + o] = v1;
    }
}

// ---------------- host orchestration ----------------
extern "C" void kernel_launch(void* const* d_in, const int* in_sizes, int n_in,
                              void* d_out, int out_size) {
    const float* xp;
    const int *ps_s, *ps_d, *rl_s, *rl_d;
    const float* prm[12];
    const float *rmw, *rmb, *rsw, *rsb;

    if (in_sizes[1] == EE) {
        xp = (const float*)d_in[0];
        ps_s = (const int*)d_in[1]; ps_d = (const int*)d_in[2];
        rl_s = (const int*)d_in[3]; rl_d = (const int*)d_in[4];
        for (int i = 0; i < 12; i++) prm[i] = (const float*)d_in[5 + i];
        rmw = (const float*)d_in[17]; rmb = (const float*)d_in[18];
        rsw = (const float*)d_in[19]; rsb = (const float*)d_in[20];
    } else {
        xp = (const float*)d_in[0];
        for (int i = 0; i < 12; i++) prm[i] = (const float*)d_in[1 + i];
        rmw = (const float*)d_in[13]; rmb = (const float*)d_in[14];
        rsw = (const float*)d_in[15]; rsb = (const float*)d_in[16];
        ps_s = (const int*)d_in[17]; ps_d = (const int*)d_in[18];
        rl_s = (const int*)d_in[19]; rl_d = (const int*)d_in[20];
    }

    float* out = (float*)d_out;

    const int s2_grp[4] = {0, 2, 1, 3};
    PP pp;
    Params p1, p2;
    for (int v = 0; v < 4; v++) {
        pp.fc[0][v] = prm[v * 3 + 0];
        pp.al[0][v] = prm[v * 3 + 1];
        pp.ar[0][v] = prm[v * 3 + 2];
        pp.fc[1][v] = prm[s2_grp[v] * 3 + 0] + HH * DD * TT;
        pp.al[1][v] = prm[s2_grp[v] * 3 + 1] + HH * DD;
        pp.ar[1][v] = prm[s2_grp[v] * 3 + 2] + HH * DD;
        p1.fc[v] = pp.fc[0][v];
        p2.fc[v] = pp.fc[1][v];
    }

    count_kernel<<<(EE + 255) / 256 + 1, 256>>>(ps_d, rl_d, pp);   // +1 block computes u
    scan_kernel<<<2, 1024>>>();
    fill_kernel<<<(EE + 255) / 256, 256>>>(ps_s, ps_d, rl_s, rl_d);

    prep_kernel<<<NN, 128>>>(xp, 0, rmw, rmb, rsw, rsb);
    gat4_kernel<<<dim3(NN / 4, 4), 128>>>(0, p1);
    reduce_stats_kernel<<<1, 256>>>();

    prep_kernel<<<NN, 128>>>(xp, 1, rmw, rmb, rsw, rsb);
    gat4_kernel<<<dim3(NN / 4, 4), 128>>>(1, p2);

    final_kernel<<<(NN * BB + 255) / 256, 256>>>(out);
}

// round 13
// speedup vs baseline: 1.1473x; 1.0786x over previous
#include <cuda_runtime.h>
#include <cstdint>

#define NN 10000
#define BB 32
#define EE 40000
#define HH 4
#define DD 10
#define TT 10
#define FP 12      // padded feat row (floats)
#define NEG 0.2f

// ---------------- scratch (zero-initialized at load; every call restores zeros) ----------------
__device__ float  g_feat[2][(size_t)NN * BB * FP];   // fp32 feats (N,B,12), 2 ch
__device__ float  g_el[4][(size_t)NN * BB * HH];     // (N,B,H) float4-friendly
__device__ float  g_er[4][(size_t)NN * BB * HH];
__device__ float  g_g[4][(size_t)NN * DD * BB];      // (N,D,B)
__device__ float  g_rm[2][(size_t)NN * BB];          // regression heads (mu, sg)
__device__ float  g_ul[2][4][HH][TT];
__device__ float  g_ur[2][4][HH][TT];
__device__ double g_stats2[4][2][256];               // bucketed LN stats (restored to 0)
__device__ double g_stats[4][2];
__device__ int    g_deg[2][NN];                      // restored to 0 by scan
__device__ int    g_rowstart[2][NN + 1];
__device__ int    g_cursor[2][NN];
__device__ int    g_csrc[2][EE];

struct Params { const float* fc[4]; };
struct PP { const float* fc[2][4]; const float* al[2][4]; const float* ar[2][4]; };

// ---------------- f32x2 helpers ----------------
__device__ __forceinline__ void fma2(unsigned long long& d, unsigned long long a, unsigned long long b) {
    asm("fma.rn.f32x2 %0, %1, %2, %0;" : "+l"(d) : "l"(a), "l"(b));
}
__device__ __forceinline__ unsigned long long pack2(float x, float y) {
    unsigned long long r; asm("mov.b64 %0, {%1, %2};" : "=l"(r) : "f"(x), "f"(y)); return r;
}
__device__ __forceinline__ void unpack2(unsigned long long v, float& x, float& y) {
    asm("mov.b64 {%0, %1}, %2;" : "=f"(x), "=f"(y) : "l"(v));
}

// ---------------- count degrees; last block computes u = W^T a ----------------
__global__ void count_kernel(const int* __restrict__ ps_dst, const int* __restrict__ rl_dst, PP p) {
    int tid = threadIdx.x;
    if (blockIdx.x == gridDim.x - 1) {
        for (int j = tid; j < 2 * 4 * HH * TT; j += 256) {
            int t = j % TT;
            int h = (j / TT) % HH;
            int v = (j / (TT * HH)) % 4;
            int s = j / (TT * HH * 4);
            float ul = 0.f, ur = 0.f;
#pragma unroll
            for (int d = 0; d < DD; d++) {
                float w = p.fc[s][v][(h * DD + d) * TT + t];
                ul += p.al[s][v][h * DD + d] * w;
                ur += p.ar[s][v][h * DD + d] * w;
            }
            g_ul[s][v][h][t] = ul;
            g_ur[s][v][h][t] = ur;
        }
        return;
    }
    int e = blockIdx.x * blockDim.x + tid;
    if (e >= EE) return;
    atomicAdd(&g_deg[0][ps_dst[e]], 1);
    atomicAdd(&g_deg[1][rl_dst[e]], 1);
}

// 2 blocks (one per graph); restores g_deg to zero for the next call
__global__ void scan_kernel() {
    __shared__ int sh[1024];
    int t = threadIdx.x;
    int g = blockIdx.x;
    const int CH = 10;
    int base = t * CH;
    int loc[CH];
    int s = 0;
#pragma unroll
    for (int i = 0; i < CH; i++) {
        int idx = base + i;
        int v = 0;
        if (idx < NN) { v = g_deg[g][idx]; g_deg[g][idx] = 0; }   // read + restore
        loc[i] = s; s += v;
    }
    sh[t] = s;
    __syncthreads();
    for (int off = 1; off < 1024; off <<= 1) {
        int v = (t >= off) ? sh[t - off] : 0;
        __syncthreads();
        sh[t] += v;
        __syncthreads();
    }
    int excl = (t > 0) ? sh[t - 1] : 0;
#pragma unroll
    for (int i = 0; i < CH; i++) {
        int idx = base + i;
        if (idx < NN) {
            int rs = excl + loc[i];
            g_rowstart[g][idx] = rs;
            g_cursor[g][idx] = rs;
        }
    }
    if (t == 1023) g_rowstart[g][NN] = sh[1023];
}

__global__ void fill_kernel(const int* __restrict__ ps_src, const int* __restrict__ ps_dst,
                            const int* __restrict__ rl_src, const int* __restrict__ rl_dst) {
    int e = blockIdx.x * blockDim.x + threadIdx.x;
    if (e >= EE) return;
    int p = atomicAdd(&g_cursor[0][ps_dst[e]], 1);
    g_csrc[0][p] = ps_src[e];
    p = atomicAdd(&g_cursor[1][rl_dst[e]], 1);
    g_csrc[1][p] = rl_src[e];
}

// ---------------- prep: feats fp32 (N,B,12) + el/er float4 (N,B,H); stage0 also rm/rs ----------------
// div/mod-free staging: u vectors copied flat; x loaded column-per-thread.
__global__ void __launch_bounds__(128) prep_kernel(const float* __restrict__ x, int stage,
                                                   const float* __restrict__ wmu, const float* __restrict__ bmu,
                                                   const float* __restrict__ wsg, const float* __restrict__ bsg) {
    __shared__ float sx[TT][BB * 3];
    __shared__ float sf[2][TT][BB];
    __shared__ float sul[4 * HH * TT], sur[4 * HH * TT];
    __shared__ float smean[4], srstd[4];
    __shared__ float swm[TT], sws[TT], sb[2];
    int n = blockIdx.x;
    int tid = threadIdx.x;
    int b = tid & 31, vv = tid >> 5;

    // flat u staging (160 floats each, contiguous): pass 1 covers 0..127, pass 2 covers 128..159
    {
        const float* ulp = &g_ul[stage][0][0][0];
        const float* urp = &g_ur[stage][0][0][0];
        sul[tid] = ulp[tid];
        sur[tid] = urp[tid];
        if (tid < 32) { sul[128 + tid] = ulp[128 + tid]; sur[128 + tid] = urp[128 + tid]; }
    }
    if (stage == 0) {
        if (tid < TT) { swm[tid] = wmu[tid]; sws[tid] = wsg[tid]; }
        if (tid == 10) sb[0] = bmu[0];
        if (tid == 11) sb[1] = bsg[0];
        // column-per-thread x load: no div/mod, coalesced 384B rows
        if (tid < 96) {
            const float* xr = x + (size_t)n * 96 + tid;
#pragma unroll
            for (int t = 0; t < TT; t++) sx[t][tid] = xr[(size_t)t * NN * 96];
        }
        __syncthreads();
        if (vv == 2) {
            float a = sb[0];
#pragma unroll
            for (int t = 0; t < TT; t++) a += sx[t][b * 3] * swm[t];
            g_rm[0][(size_t)n * BB + b] = a;
        } else if (vv == 3) {
            float a = sb[1];
#pragma unroll
            for (int t = 0; t < TT; t++) a += sx[t][b * 3 + 1] * sws[t];
            g_rm[1][(size_t)n * BB + b] = a;
        }
    } else {
        if (tid < 4) {
            const double invn = 1.0 / ((double)NN * DD * BB);
            double mean = g_stats[tid][0] * invn;
            double var = g_stats[tid][1] * invn - mean * mean;
            smean[tid] = (float)mean;
            srstd[tid] = (float)rsqrt(var + 1e-5);
        }
        __syncthreads();
        // i = t*32 + bb: power-of-2 split, cheap
        for (int i = tid; i < TT * BB; i += 128) {
            int t = i >> 5, bb = i & 31;
            size_t gi = ((size_t)n * DD + t) * BB + bb;
            float v0 = (g_g[0][gi] - smean[0]) * srstd[0];
            float v1 = (g_g[1][gi] - smean[1]) * srstd[1];
            float v2 = (g_g[2][gi] - smean[2]) * srstd[2];
            float v3 = (g_g[3][gi] - smean[3]) * srstd[3];
            sf[0][t][bb] = 0.5f * (v0 + v1);
            sf[1][t][bb] = 0.5f * (v2 + v3);
        }
        __syncthreads();
    }

    // per-thread feature vector for channel ch = vv&1
    int ch = vv & 1;
    float f[TT];
    if (stage == 0) {
        int col = b * 3 + ch;
#pragma unroll
        for (int t = 0; t < TT; t++) f[t] = sx[t][col];
    } else {
#pragma unroll
        for (int t = 0; t < TT; t++) f[t] = sf[ch][t][b];
    }

    // feat write (warps 0,1 == channels 0,1; f is exactly that channel)
    if (vv < 2) {
        float4* dstp = (float4*)&g_feat[vv][((size_t)n * BB + b) * FP];
        dstp[0] = make_float4(f[0], f[1], f[2], f[3]);
        dstp[1] = make_float4(f[4], f[5], f[6], f[7]);
        dstp[2] = make_float4(f[8], f[9], 0.f, 0.f);
    }

    const float* ulv = &sul[vv * HH * TT];
    const float* urv = &sur[vv * HH * TT];
    float elh[HH], erh[HH];
#pragma unroll
    for (int h = 0; h < HH; h++) {
        float a = 0.f, c = 0.f;
#pragma unroll
        for (int t = 0; t < TT; t++) { a += ulv[h * TT + t] * f[t]; c += urv[h * TT + t] * f[t]; }
        elh[h] = a; erh[h] = c;
    }
    size_t eb = ((size_t)n * BB + b) * HH;
    *(float4*)&g_el[vv][eb] = make_float4(elh[0], elh[1], elh[2], elh[3]);
    *(float4*)&g_er[vv][eb] = make_float4(erh[0], erh[1], erh[2], erh[3]);
}

// ---------------- GAT: one warp per (dst, variant), all 4 heads, 2-edge pipelined ----------------
__global__ void __launch_bounds__(128) gat4_kernel(int stage, Params p) {
    __shared__ unsigned long long sWp[HH * DD * 5];
    int v = blockIdx.y;
    int graph = stage ? (v & 1) : (v >> 1);
    int tid = threadIdx.x;
    int b = tid & 31, w = tid >> 5;
    int dst = blockIdx.x * 4 + w;

    int s0 = g_rowstart[graph][dst];
    int deg = g_rowstart[graph][dst + 1] - s0;
    float4 e4 = *(const float4*)&g_er[v][((size_t)dst * BB + b) * HH];

    // stage W (ordered before epilogue by the post-mainloop barrier)
    for (int i = tid; i < HH * DD * 5; i += 128) {
        int row = i / 5, tp = i % 5;
        sWp[i] = pack2(p.fc[v][row * TT + 2 * tp], p.fc[v][row * TT + 2 * tp + 1]);
    }

    float erh[HH] = {e4.x, e4.y, e4.z, e4.w};
    const float4* el4 = (const float4*)g_el[v];
    const float* featb = g_feat[v & 1];

    unsigned long long acc[HH][5];
    float Z[HH];
#pragma unroll
    for (int h = 0; h < HH; h++) {
        Z[h] = 0.f;
#pragma unroll
        for (int t = 0; t < 5; t++) acc[h][t] = 0ull;
    }

    for (int base = 0; base < deg; base += 32) {
        int cnt = min(32, deg - base);
        int myS = (b < cnt) ? g_csrc[graph][s0 + base + b] : 0;
        int k = 0;
        for (; k + 1 < cnt; k += 2) {
            int sA = __shfl_sync(0xffffffffu, myS, k);
            int sB = __shfl_sync(0xffffffffu, myS, k + 1);
            size_t sbA = (size_t)sA * BB + b;
            size_t sbB = (size_t)sB * BB + b;
            float4 evA = el4[sbA];
            float4 evB = el4[sbB];
            const float4* fbA = (const float4*)(featb + sbA * FP);
            const float4* fbB = (const float4*)(featb + sbB * FP);
            float4 fA0 = fbA[0], fA1 = fbA[1], fA2 = fbA[2];
            float4 fB0 = fbB[0], fB1 = fbB[1], fB2 = fbB[2];

            unsigned long long fpA[5], fpB[5];
            fpA[0] = pack2(fA0.x, fA0.y); fpA[1] = pack2(fA0.z, fA0.w);
            fpA[2] = pack2(fA1.x, fA1.y); fpA[3] = pack2(fA1.z, fA1.w);
            fpA[4] = pack2(fA2.x, fA2.y);
            fpB[0] = pack2(fB0.x, fB0.y); fpB[1] = pack2(fB0.z, fB0.w);
            fpB[2] = pack2(fB1.x, fB1.y); fpB[3] = pack2(fB1.z, fB1.w);
            fpB[4] = pack2(fB2.x, fB2.y);
            float evhA[HH] = {evA.x, evA.y, evA.z, evA.w};
            float evhB[HH] = {evB.x, evB.y, evB.z, evB.w};
#pragma unroll
            for (int h = 0; h < HH; h++) {
                float valA = evhA[h] + erh[h];
                valA = (valA >= 0.f) ? valA : NEG * valA;
                float valB = evhB[h] + erh[h];
                valB = (valB >= 0.f) ? valB : NEG * valB;
                float wA = __expf(valA);     // |val| small: max-free softmax exact
                float wB = __expf(valB);
                Z[h] += wA + wB;
                unsigned long long wpA = pack2(wA, wA);
                unsigned long long wpB = pack2(wB, wB);
#pragma unroll
                for (int tp = 0; tp < 5; tp++) {
                    fma2(acc[h][tp], fpA[tp], wpA);
                    fma2(acc[h][tp], fpB[tp], wpB);
                }
            }
        }
        if (k < cnt) {
            int s = __shfl_sync(0xffffffffu, myS, k);
            size_t sb = (size_t)s * BB + b;
            float4 ev = el4[sb];
            const float4* fb = (const float4*)(featb + sb * FP);
            float4 f0 = fb[0], f1 = fb[1], f2 = fb[2];
            unsigned long long fp[5];
            fp[0] = pack2(f0.x, f0.y); fp[1] = pack2(f0.z, f0.w);
            fp[2] = pack2(f1.x, f1.y); fp[3] = pack2(f1.z, f1.w);
            fp[4] = pack2(f2.x, f2.y);
            float evh[HH] = {ev.x, ev.y, ev.z, ev.w};
#pragma unroll
            for (int h = 0; h < HH; h++) {
                float val = evh[h] + erh[h];
                val = (val >= 0.f) ? val : NEG * val;
                float wh = __expf(val);
                Z[h] += wh;
                unsigned long long wp = pack2(wh, wh);
#pragma unroll
                for (int tp = 0; tp < 5; tp++) fma2(acc[h][tp], fp[tp], wp);
            }
        }
    }

    __syncthreads();   // orders all sWp writes before epilogue reads (off the startup path)

    // epilogue: W matvec (packed) + leaky + head mean
    float outd[DD];
#pragma unroll
    for (int d = 0; d < DD; d++) outd[d] = 0.f;
#pragma unroll
    for (int h = 0; h < HH; h++) {
        float inv = (deg > 0) ? (0.25f / Z[h]) : 0.f;
#pragma unroll
        for (int d = 0; d < DD; d++) {
            unsigned long long o2 = 0ull;
#pragma unroll
            for (int tp = 0; tp < 5; tp++) fma2(o2, acc[h][tp], sWp[(h * DD + d) * 5 + tp]);
            float ox, oy; unpack2(o2, ox, oy);
            float o = (ox + oy) * inv;   // leaky(x)*0.25 == leaky(x*0.25)
            o = (o >= 0.f) ? o : NEG * o;
            outd[d] += o;
        }
    }

    float ls = 0.f, lss = 0.f;
    float* gout = g_g[v];
#pragma unroll
    for (int d = 0; d < DD; d++) {
        gout[((size_t)dst * DD + d) * BB + b] = outd[d];
        ls += outd[d]; lss += outd[d] * outd[d];
    }
    if (stage == 0) {
#pragma unroll
        for (int off = 16; off; off >>= 1) {
            ls += __shfl_down_sync(0xffffffffu, ls, off);
            lss += __shfl_down_sync(0xffffffffu, lss, off);
        }
        if (b == 0) {
            atomicAdd(&g_stats2[v][0][dst & 255], (double)ls);
            atomicAdd(&g_stats2[v][1][dst & 255], (double)lss);
        }
    }
}

// ---------------- reduce bucketed stats; restores g_stats2 to zero ----------------
__global__ void reduce_stats_kernel() {
    int w = threadIdx.x >> 5;
    int lane = threadIdx.x & 31;
    int slot = w >> 1, j = w & 1;
    double s = 0.0;
    for (int i = lane; i < 256; i += 32) {
        s += g_stats2[slot][j][i];
        g_stats2[slot][j][i] = 0.0;      // restore for next call
    }
#pragma unroll
    for (int off = 16; off; off >>= 1) s += __shfl_down_sync(0xffffffffu, s, off);
    if (lane == 0) g_stats[slot][j] = s;
}

// ---------------- final combine (rm/rs precomputed) ----------------
__global__ void final_kernel(float* __restrict__ out) {
    int i = blockIdx.x * blockDim.x + threadIdx.x;
    if (i >= NN * BB) return;
    int b = i & 31;
    int n = i >> 5;
    float rm = g_rm[0][i];
    float rs = g_rm[1][i];
    const float third = 1.f / 3.f;
#pragma unroll
    for (int d = 0; d < DD; d++) {
        size_t gi = ((size_t)n * DD + d) * BB + b;
        float v0 = (rm + g_g[0][gi] + g_g[1][gi]) * third;
        float v1 = (rs + g_g[2][gi] + g_g[3][gi]) * third;
        size_t o = ((size_t)n * BB + b) * DD + d;
        out[o] = v0;
        out[(size_t)NN * BB * DD + o] = v1;
    }
}

// ---------------- host orchestration ----------------
extern "C" void kernel_launch(void* const* d_in, const int* in_sizes, int n_in,
                              void* d_out, int out_size) {
    const float* xp;
    const int *ps_s, *ps_d, *rl_s, *rl_d;
    const float* prm[12];
    const float *rmw, *rmb, *rsw, *rsb;

    if (in_sizes[1] == EE) {
        xp = (const float*)d_in[0];
        ps_s = (const int*)d_in[1]; ps_d = (const int*)d_in[2];
        rl_s = (const int*)d_in[3]; rl_d = (const int*)d_in[4];
        for (int i = 0; i < 12; i++) prm[i] = (const float*)d_in[5 + i];
        rmw = (const float*)d_in[17]; rmb = (const float*)d_in[18];
        rsw = (const float*)d_in[19]; rsb = (const float*)d_in[20];
    } else {
        xp = (const float*)d_in[0];
        for (int i = 0; i < 12; i++) prm[i] = (const float*)d_in[1 + i];
        rmw = (const float*)d_in[13]; rmb = (const float*)d_in[14];
        rsw = (const float*)d_in[15]; rsb = (const float*)d_in[16];
        ps_s = (const int*)d_in[17]; ps_d = (const int*)d_in[18];
        rl_s = (const int*)d_in[19]; rl_d = (const int*)d_in[20];
    }

    float* out = (float*)d_out;

    const int s2_grp[4] = {0, 2, 1, 3};
    PP pp;
    Params p1, p2;
    for (int v = 0; v < 4; v++) {
        pp.fc[0][v] = prm[v * 3 + 0];
        pp.al[0][v] = prm[v * 3 + 1];
        pp.ar[0][v] = prm[v * 3 + 2];
        pp.fc[1][v] = prm[s2_grp[v] * 3 + 0] + HH * DD * TT;
        pp.al[1][v] = prm[s2_grp[v] * 3 + 1] + HH * DD;
        pp.ar[1][v] = prm[s2_grp[v] * 3 + 2] + HH * DD;
        p1.fc[v] = pp.fc[0][v];
        p2.fc[v] = pp.fc[1][v];
    }

    count_kernel<<<(EE + 255) / 256 + 1, 256>>>(ps_d, rl_d, pp);   // +1 block computes u
    scan_kernel<<<2, 1024>>>();
    fill_kernel<<<(EE + 255) / 256, 256>>>(ps_s, ps_d, rl_s, rl_d);

    prep_kernel<<<NN, 128>>>(xp, 0, rmw, rmb, rsw, rsb);
    gat4_kernel<<<dim3(NN / 4, 4), 128>>>(0, p1);
    reduce_stats_kernel<<<1, 256>>>();

    prep_kernel<<<NN, 128>>>(xp, 1, rmw, rmb, rsw, rsb);
    gat4_kernel<<<dim3(NN / 4, 4), 128>>>(1, p2);

    final_kernel<<<(NN * BB + 255) / 256, 256>>>(out);
}